// round 8
// baseline (speedup 1.0000x reference)
#include <cuda_runtime.h>
#include <cuda_bf16.h>
#include <cstdint>

// scatter_mean: out[m, c] = sum_{i: idx[i]==m} in[i, c] / max(count_m, 1)
// N = 4,000,000 rows, C = 16 channels fp32, M = 500,000 segments, idx int32.
//
// Hybrid scatter: REDG warps (LSU pipe) + bulk-reduce warps (TMA pipe).
// Measured rates (R7): REDG ~19.25 us/Mrow (per-SM LSU-bound, warp-count
// independent), TMA path ~57.3 us/Mrow for 3 warps. Balanced split: 3M:1M.

#define CHANNELS 16
#define MAX_SEGMENTS 500000
#define W_REDG 5
#define W_TMA  3

__device__ float g_counts[MAX_SEGMENTS];

// ---------------------------------------------------------------------------
// Hybrid scatter.
// ---------------------------------------------------------------------------
__global__ void __launch_bounds__(256, 8)
dve_scatter_hybrid(const float4* __restrict__ in,
                   const int* __restrict__ idx,
                   float4* __restrict__ sums4,
                   int n, int n_redg) {
    // Staging: 3 TMA warps x 2 buffers x 32 rows x 64B = 12 KB.
    __shared__ __align__(128) float4 stage[W_TMA * 2 * 32 * 4];

    int wid = threadIdx.x >> 5;
    int lane = threadIdx.x & 31;

    if (wid < W_REDG) {
        // ---- REDG path: quad-per-row, 8 rows per warp-iter, rows [0, n_redg)
        int warp_global = blockIdx.x * W_REDG + wid;
        int stride = gridDim.x * W_REDG * 8;
        int q = lane & 3;
        for (int base = warp_global * 8; base < n_redg; base += stride) {
            int row = base + (lane >> 2);
            if (row < n_redg) {
                int s = __ldg(idx + row);
                float4 v = __ldg(in + (size_t)row * 4 + q);
                float4* p = sums4 + (size_t)s * 4 + q;
                asm volatile("red.global.add.v4.f32 [%0], {%1, %2, %3, %4};"
                             :: "l"(p), "f"(v.x), "f"(v.y), "f"(v.z), "f"(v.w)
                             : "memory");
                if (q == 0)
                    atomicAdd(&g_counts[s], 1.0f);
            }
        }
    } else {
        // ---- TMA path: one row per lane per iter, rows [n_redg, n).
        int tw = wid - W_REDG;
        int warp_global = blockIdx.x * W_TMA + tw;
        int stride = gridDim.x * W_TMA * 32;
        int it = 0;
        for (long long base = (long long)n_redg + (long long)warp_global * 32;
             base < n; base += stride, ++it) {
            int buf = it & 1;
            float4* slot = &stage[((tw * 2 + buf) * 32 + lane) * 4];

            // Ensure the bulk op issued 2 iters ago on this buffer has read it.
            asm volatile("cp.async.bulk.wait_group 1;" ::: "memory");

            long long row = base + lane;
            bool active = row < n;
            int s = 0;
            if (active) {
                s = __ldg(idx + row);
                const float4* src = in + row * 4;
                slot[0] = __ldg(src + 0);
                slot[1] = __ldg(src + 1);
                slot[2] = __ldg(src + 2);
                slot[3] = __ldg(src + 3);
            }
            // Generic-proxy STS must be visible to the async proxy.
            asm volatile("fence.proxy.async.shared::cta;" ::: "memory");

            if (active) {
                uint32_t saddr = (uint32_t)__cvta_generic_to_shared(slot);
                float* dst = (float*)(sums4 + (size_t)s * 4);
                asm volatile(
                    "cp.reduce.async.bulk.global.shared::cta.bulk_group.add.f32 "
                    "[%0], [%1], 64;"
                    :: "l"(dst), "r"(saddr) : "memory");
                atomicAdd(&g_counts[s], 1.0f);
            }
            asm volatile("cp.async.bulk.commit_group;" ::: "memory");
        }
        asm volatile("cp.async.bulk.wait_group 0;" ::: "memory");
    }
}

// ---------------------------------------------------------------------------
// Finalize: one float4 per thread (4 threads per segment), pure bandwidth.
// ---------------------------------------------------------------------------
__global__ void __launch_bounds__(256, 8)
dve_finalize_kernel(float4* __restrict__ out, int total4) {
    int t = blockIdx.x * blockDim.x + threadIdx.x;
    if (t >= total4) return;

    int seg = t >> 2;
    float inv = 1.0f / fmaxf(g_counts[seg], 1.0f);

    float4 v = out[t];
    v.x *= inv; v.y *= inv; v.z *= inv; v.w *= inv;
    out[t] = v;
}

// ---------------------------------------------------------------------------
// Launch
// ---------------------------------------------------------------------------
extern "C" void kernel_launch(void* const* d_in, const int* in_sizes, int n_in,
                              void* d_out, int out_size) {
    const float4* in = (const float4*)d_in[0];   // [N, 16] fp32
    const int* idx = (const int*)d_in[1];        // [N] int32
    float* out = (float*)d_out;                  // [M, 16] fp32

    int n = in_sizes[0] / CHANNELS;   // 4,000,000
    int m = out_size / CHANNELS;      // 500,000

    // Balanced split from measured rates: REDG 19.25 us/Mrow, TMA 57.3 us/Mrow
    // -> REDG gets 3/4 of rows, TMA warps get 1/4.
    int n_redg = (int)((long long)n * 3 / 4);

    void* counts_ptr = nullptr;
    cudaGetSymbolAddress(&counts_ptr, g_counts);
    cudaMemsetAsync(d_out, 0, (size_t)out_size * sizeof(float), 0);
    cudaMemsetAsync(counts_ptr, 0, (size_t)m * sizeof(float), 0);

    {
        int threads = 256;
        int blocks = 2048;
        dve_scatter_hybrid<<<blocks, threads>>>(in, idx, (float4*)out, n, n_redg);
    }
    {
        int threads = 256;
        int total4 = m * 4;                       // 2,000,000 float4s
        int blocks = (total4 + threads - 1) / threads;
        dve_finalize_kernel<<<blocks, threads>>>((float4*)out, total4);
    }
}

// round 9
// speedup vs baseline: 1.1085x; 1.1085x over previous
#include <cuda_runtime.h>
#include <cuda_bf16.h>

// scatter_mean: out[m, c] = sum_{i: idx[i]==m} in[i, c] / max(count_m, 1)
// N = 4,000,000 rows, C = 16 channels fp32, M = 500,000 segments, idx int32.
//
// Final structure (R8 falsified the TMA-hybrid: bulk-reduce enqueue shares
// the per-SM LSU command path with REDG, so splitting gains nothing):
//   memsets (HW fill, ~5us) -> pure quad-REDG scatter (per-SM command floor,
//   ~77us for 20M reduction lanes) -> finalize with MLP=4/thread (~10us).

#define CHANNELS 16
#define MAX_SEGMENTS 500000

__device__ float g_counts[MAX_SEGMENTS];

// ---------------------------------------------------------------------------
// Scatter-add, 4 lanes per row (quad-per-row). Each lane: 1 float4 load +
// 1 red.global.add.v4.f32 (16B); quad covers one 64B destination row.
// Lane 0 of each quad adds the count. (R6 form — measured at the floor.)
// ---------------------------------------------------------------------------
__global__ void __launch_bounds__(256, 8)
dve_scatter_kernel(const float4* __restrict__ in,
                   const int* __restrict__ idx,
                   float4* __restrict__ sums4,
                   int n) {
    int t = blockIdx.x * blockDim.x + threadIdx.x;   // [0, 4n)
    int row = t >> 2;
    int q = t & 3;
    if (row >= n) return;

    int s = __ldg(idx + row);                         // quad lanes share a sector
    float4 v = __ldg(in + (size_t)row * 4 + q);       // warp reads 8 rows = 512B

    float4* p = sums4 + (size_t)s * 4 + q;            // quad covers one 64B row
    asm volatile("red.global.add.v4.f32 [%0], {%1, %2, %3, %4};"
                 :: "l"(p), "f"(v.x), "f"(v.y), "f"(v.z), "f"(v.w) : "memory");

    if (q == 0)
        atomicAdd(&g_counts[s], 1.0f);
}

// ---------------------------------------------------------------------------
// Finalize: 2 float4s per thread via grid-stride, all 4 loads (2 data + 2
// count) issued before any dependent math -> MLP=4 hides the ~234cyc L2
// latency that bound the one-element version. Warp count stays huge (4M
// threads) so occupancy-side latency hiding is preserved.
// ---------------------------------------------------------------------------
__global__ void __launch_bounds__(256, 8)
dve_finalize_kernel(float4* __restrict__ out, int total4) {
    int stride = gridDim.x * blockDim.x;
    int t0 = blockIdx.x * blockDim.x + threadIdx.x;
    int t1 = t0 + stride;

    if (t1 < total4) {
        float c0 = g_counts[t0 >> 2];
        float c1 = g_counts[t1 >> 2];
        float4 v0 = out[t0];
        float4 v1 = out[t1];
        float i0 = 1.0f / fmaxf(c0, 1.0f);
        float i1 = 1.0f / fmaxf(c1, 1.0f);
        v0.x *= i0; v0.y *= i0; v0.z *= i0; v0.w *= i0;
        v1.x *= i1; v1.y *= i1; v1.z *= i1; v1.w *= i1;
        out[t0] = v0;
        out[t1] = v1;
    } else if (t0 < total4) {
        float inv = 1.0f / fmaxf(g_counts[t0 >> 2], 1.0f);
        float4 v = out[t0];
        v.x *= inv; v.y *= inv; v.z *= inv; v.w *= inv;
        out[t0] = v;
    }
}

// ---------------------------------------------------------------------------
// Launch
// ---------------------------------------------------------------------------
extern "C" void kernel_launch(void* const* d_in, const int* in_sizes, int n_in,
                              void* d_out, int out_size) {
    const float4* in = (const float4*)d_in[0];   // [N, 16] fp32
    const int* idx = (const int*)d_in[1];        // [N] int32
    float* out = (float*)d_out;                  // [M, 16] fp32

    int n = in_sizes[0] / CHANNELS;   // 4,000,000
    int m = out_size / CHANNELS;      // 500,000

    // Zero sums + counts via HW memset nodes (graph-capturable, no alloc).
    void* counts_ptr = nullptr;
    cudaGetSymbolAddress(&counts_ptr, g_counts);
    cudaMemsetAsync(d_out, 0, (size_t)out_size * sizeof(float), 0);
    cudaMemsetAsync(counts_ptr, 0, (size_t)m * sizeof(float), 0);

    {
        int threads = 256;
        long long total = (long long)n * 4;
        int blocks = (int)((total + threads - 1) / threads);
        dve_scatter_kernel<<<blocks, threads>>>(in, idx, (float4*)out, n);
    }
    {
        int threads = 256;
        int total4 = m * 4;                       // 2,000,000 float4s
        int per_block = threads * 2;
        int blocks = (total4 + per_block - 1) / per_block;  // 3907
        dve_finalize_kernel<<<blocks, threads>>>((float4*)out, total4);
    }
}